// round 14
// baseline (speedup 1.0000x reference)
#include <cuda_runtime.h>
#include <cuda_fp16.h>
#include <cstdint>

// ============================================================================
// out = LayerNorm(relu(x @ (m*W_v + (1-m)*W_r)))   [attention path is identity:
// softmax rows sum to 1 and the reference einsum contracts the softmax axis]
//   x: [131072, 256] f32,  W: [256, 512] f32,  out: [131072, 512] f32
// R14 = R13 stack (warp-role specialization + persistent CTAs + cross-tile
// prefetch + ldcs/stcs) PLUS resident B: KC=32, chunks 0-3 live in smem for
// the CTA's lifetime, chunks 4-7 stream through a 2-stage ring. Halves the
// loader warps' cp.async issue work (now the critical path) and gives four
// of eight regions zero B-issue work.
// fp16 mma.sync, 64x64 warp tiles, BM=64, NT=256.
// ============================================================================

static constexpr int K_DIM  = 256;
static constexpr int N_DIM  = 512;
static constexpr int BM     = 64;
static constexpr int KC     = 32;
static constexpr int NCH    = K_DIM / KC;   // 8
static constexpr int NTILES = 131072 / BM;  // 2048
static constexpr int NT     = 256;          // 8 warps; warp = 64 rows x 64 cols
static constexpr int GRID   = 148;

// SMEM layout (bytes)
static constexpr int SM_BRES = 0;           // 4 x 32768 = 128 KB (chunks 0-3, persistent)
static constexpr int SM_BSTR = 131072;      // 2 x 32768 = 64 KB (ring: chunks 4-7)
static constexpr int SM_A    = 196608;      // 2 x 8192 = 16 KB (A double buffer)
static constexpr int SM_GB   = 212992;      // gamma/beta f32 = 4 KB
static constexpr int SM_PS   = 217088;      // psum[64][8]+psq[64][8]+stats[64][2] = 4608
static constexpr int SMEM_TOTAL = 221696;

// Pre-swizzled fp16 B chunk images (KC=32 packed: 2 n-rows per 128B line):
// off(n, kk) = swz((n>>1)*128 + (n&1)*64 + kk*2), kk = k % 32, chunk = k / 32.
__device__ __align__(16) unsigned char g_Bimg[NCH][32768];

// ---------------------------------------------------------------------------
__device__ __forceinline__ uint32_t smem_u32(const void* p) {
    uint32_t r;
    asm("{ .reg .u64 t; cvta.to.shared.u64 t, %1; cvt.u32.u64 %0, t; }" : "=r"(r) : "l"(p));
    return r;
}
__host__ __device__ __forceinline__ uint32_t swz(uint32_t o) { return o ^ ((o >> 3) & 0x70); }

__device__ __forceinline__ void cp16(uint32_t d, const void* s) {
    asm volatile("cp.async.cg.shared.global [%0], [%1], 16;" :: "r"(d), "l"(s));
}
__device__ __forceinline__ void cp_commit() { asm volatile("cp.async.commit_group;"); }
__device__ __forceinline__ void cp_wait0()  { asm volatile("cp.async.wait_group 0;"); }

__device__ __forceinline__ float4 ldcs4(const float* p) {
    float4 v;
    asm volatile("ld.global.cs.v4.f32 {%0,%1,%2,%3}, [%4];"
                 : "=f"(v.x), "=f"(v.y), "=f"(v.z), "=f"(v.w) : "l"(p));
    return v;
}
__device__ __forceinline__ void stcs2(float* p, float a, float b) {
    asm volatile("st.global.cs.v2.f32 [%0], {%1,%2};" :: "l"(p), "f"(a), "f"(b) : "memory");
}

__device__ __forceinline__ void ldsm4(uint32_t* r, uint32_t a) {
    asm volatile("ldmatrix.sync.aligned.m8n8.x4.shared.b16 {%0,%1,%2,%3}, [%4];"
                 : "=r"(r[0]), "=r"(r[1]), "=r"(r[2]), "=r"(r[3]) : "r"(a));
}
__device__ __forceinline__ void hmma(float* c, const uint32_t* a, const uint32_t* b) {
    asm volatile("mma.sync.aligned.m16n8k16.row.col.f32.f16.f16.f32 "
                 "{%0,%1,%2,%3},{%4,%5,%6,%7},{%8,%9},{%0,%1,%2,%3};"
                 : "+f"(c[0]), "+f"(c[1]), "+f"(c[2]), "+f"(c[3])
                 : "r"(a[0]), "r"(a[1]), "r"(a[2]), "r"(a[3]), "r"(b[0]), "r"(b[1]));
}

// ---------------------------------------------------------------------------
// Prep: W_c = m*W_v + (1-m)*W_r -> fp16, pre-swizzled packed chunk images.
// ---------------------------------------------------------------------------
__global__ void prep_kernel(const float* __restrict__ Wv, const float* __restrict__ Wr,
                            const float* __restrict__ mix) {
    int gid = blockIdx.x * blockDim.x + threadIdx.x;
    if (gid >= K_DIM * N_DIM) return;
    int n = gid & 511;
    int k = gid >> 9;
    float m = 1.0f / (1.0f + expf(-mix[0]));
    float w = m * Wv[k * N_DIM + n] + (1.0f - m) * Wr[k * N_DIM + n];
    int c  = k >> 5;
    int kk = k & 31;
    uint32_t off = swz((uint32_t)((n >> 1) * 128 + (n & 1) * 64 + kk * 2));
    *(__half*)(&g_Bimg[c][off]) = __float2half(w);
}

// ---------------------------------------------------------------------------
// Persistent fused GEMM (fp16 mma.sync, specialized, resident B) + relu + LN
// ---------------------------------------------------------------------------
__global__ void __launch_bounds__(NT, 1)
gemm_ln_kernel(const float* __restrict__ x, const float* __restrict__ gamma,
               const float* __restrict__ beta, float* __restrict__ out) {
    extern __shared__ char smem[];
    const uint32_t sb = smem_u32(smem);
    const int tid  = threadIdx.x;
    const int wn   = tid >> 5;    // warp 0..7 -> 64-col slice, all 64 rows
    const int lane = tid & 31;
    const bool loader = (wn < 4); // one loader warp per SMSP
    const int bid  = blockIdx.x;

    // gamma/beta into smem (once)
    {
        float* gsh = (float*)(smem + SM_GB);
        for (int i = tid; i < N_DIM; i += NT) {
            gsh[i]         = gamma[i];
            gsh[N_DIM + i] = beta[i];
        }
    }

    // ldmatrix base offsets (KC=32 packed B layout)
    const uint32_t arow = (uint32_t)((lane & 15) * 128 + (lane >> 4) * 16);   // + mt*2048 + ks*32
    const int nb = wn * 64 + ((lane >> 4) & 1) * 8 + (lane & 7);
    const uint32_t brow = (uint32_t)((nb >> 1) * 128 + (nb & 1) * 64 + ((lane >> 3) & 1) * 16); // + bt*1024 + ks*32

    // Loader A indexing: 512 float4 per chunk over 128 loader threads -> 4 each
    int arowi[4], asegi[4];
    uint32_t asoff[4];
    #pragma unroll
    for (int i = 0; i < 4; i++) {
        int idx = tid + i * 128;           // 0..511
        arowi[i] = idx >> 3;               // 0..63
        asegi[i] = (idx & 7) * 4;
        asoff[i] = swz((uint32_t)((idx >> 3) * 128 + (idx & 7) * 8));
    }

    float* psum  = (float*)(smem + SM_PS);
    float* psq   = psum + 512;
    float* stats = psq + 512;
    const float* gsh = (const float*)(smem + SM_GB);
    const float* bsh = gsh + N_DIM;

    float4 av[4];
    // ---- one-time prologue (loader warps): resident B0-3; A(t0,c0) STS; c1 LDG ----
    if (loader) {
        #pragma unroll
        for (int i = 0; i < 64; i++) {
            int j = tid + i * 128;         // 0..8191 (4 chunks x 2048 x 16B)
            int c = j >> 11;
            int o = (j & 2047) * 16;
            cp16(sb + SM_BRES + c * 32768 + o, &g_Bimg[c][o]);
        }
        cp_commit();
        const size_t mb = (size_t)bid * BM;
        #pragma unroll
        for (int i = 0; i < 4; i++)
            av[i] = ldcs4(x + (mb + arowi[i]) * K_DIM + asegi[i]);
        cp_wait0();
        #pragma unroll
        for (int i = 0; i < 4; i++) {
            __half2 h01 = __floats2half2_rn(av[i].x, av[i].y);
            __half2 h23 = __floats2half2_rn(av[i].z, av[i].w);
            *(uint2*)(smem + SM_A + asoff[i]) = make_uint2(*(uint32_t*)&h01, *(uint32_t*)&h23);
        }
        #pragma unroll
        for (int i = 0; i < 4; i++)
            av[i] = ldcs4(x + (mb + arowi[i]) * K_DIM + KC + asegi[i]);
    }

    for (int t = bid; t < NTILES; t += GRID) {
        const size_t m0 = (size_t)t * BM;
        const bool last_tile = (t + GRID >= NTILES);

        float acc[4][8][4];
        #pragma unroll
        for (int mt = 0; mt < 4; mt++)
            #pragma unroll
            for (int nt = 0; nt < 8; nt++)
                #pragma unroll
                for (int i = 0; i < 4; i++) acc[mt][nt][i] = 0.0f;

        #pragma unroll
        for (int c = 0; c < NCH; c++) {
            // loader: wait for streamed B stage before consuming it
            if (loader && c >= 4) cp_wait0();
            __syncthreads();               // publish A stage c (+ stream stage); order reuse

            if (loader) {
                // A: STS chunk c+1, LDG chunk c+2 (cross-tile at the seam)
                const bool has_nextA = !(last_tile && c == NCH - 1);
                if (has_nextA) {
                    const int nst = (c + 1) & 1;
                    #pragma unroll
                    for (int i = 0; i < 4; i++) {
                        __half2 h01 = __floats2half2_rn(av[i].x, av[i].y);
                        __half2 h23 = __floats2half2_rn(av[i].z, av[i].w);
                        *(uint2*)(smem + SM_A + nst * 8192 + asoff[i]) =
                            make_uint2(*(uint32_t*)&h01, *(uint32_t*)&h23);
                    }
                    if (c < NCH - 2) {
                        #pragma unroll
                        for (int i = 0; i < 4; i++)
                            av[i] = ldcs4(x + (m0 + arowi[i]) * K_DIM + (c + 2) * KC + asegi[i]);
                    } else if (!last_tile) {
                        const size_t mn = (size_t)(t + GRID) * BM;
                        #pragma unroll
                        for (int i = 0; i < 4; i++)
                            av[i] = ldcs4(x + (mn + arowi[i]) * K_DIM + (c - 6) * KC + asegi[i]);
                    }
                }
                // B stream issues: c4@r0, c5@r1, c6@r5, c7@r6 (stage hazards
                // ordered by region-entry barriers; leads 4,4,1,1 regions)
                int sc = -1;
                if (c == 0) sc = 4;
                else if (c == 1) sc = 5;
                else if (c == 5) sc = 6;
                else if (c == 6) sc = 7;
                if (sc >= 0) {
                    const uint32_t dst = sb + SM_BSTR + ((sc - 4) & 1) * 32768;
                    const unsigned char* bimg = &g_Bimg[sc][0];
                    #pragma unroll
                    for (int i = 0; i < 16; i++) {
                        int j = tid + i * 128;     // 0..2047
                        cp16(dst + j * 16, bimg + j * 16);
                    }
                    cp_commit();
                }
            }

            // ---- MMA chunk c (all warps; MMA-only warps start immediately) ----
            const uint32_t Ab = sb + SM_A + (c & 1) * 8192;
            const uint32_t Bb = (c < 4) ? (sb + SM_BRES + c * 32768)
                                        : (sb + SM_BSTR + ((c - 4) & 1) * 32768);
            uint32_t af[2][4][4];
            #pragma unroll
            for (int ks = 0; ks < 2; ks++)
                #pragma unroll
                for (int mt = 0; mt < 4; mt++)
                    ldsm4(af[ks][mt], Ab + swz(arow + mt * 2048 + ks * 32));
            #pragma unroll
            for (int ks = 0; ks < 2; ks++) {
                #pragma unroll
                for (int bt = 0; bt < 4; bt++) {
                    uint32_t bh[4];
                    ldsm4(bh, Bb + swz(brow + bt * 1024 + ks * 32));
                    #pragma unroll
                    for (int mt = 0; mt < 4; mt++) {
                        hmma(acc[mt][2 * bt],     af[ks][mt], &bh[0]);
                        hmma(acc[mt][2 * bt + 1], af[ks][mt], &bh[2]);
                    }
                }
            }
        }

        // ---------------- Epilogue: relu + LayerNorm(512) ----------------
        #pragma unroll
        for (int mt = 0; mt < 4; mt++) {
            #pragma unroll
            for (int half = 0; half < 2; half++) {
                float s = 0.0f, q = 0.0f;
                #pragma unroll
                for (int nt = 0; nt < 8; nt++) {
                    float v0 = fmaxf(acc[mt][nt][half * 2 + 0], 0.0f);
                    float v1 = fmaxf(acc[mt][nt][half * 2 + 1], 0.0f);
                    s += v0 + v1;
                    q = fmaf(v0, v0, q);
                    q = fmaf(v1, v1, q);
                }
                s += __shfl_xor_sync(0xFFFFFFFFu, s, 1);
                q += __shfl_xor_sync(0xFFFFFFFFu, q, 1);
                s += __shfl_xor_sync(0xFFFFFFFFu, s, 2);
                q += __shfl_xor_sync(0xFFFFFFFFu, q, 2);
                if ((lane & 3) == 0) {
                    int r = mt * 16 + (lane >> 2) + half * 8;
                    psum[r * 8 + wn] = s;
                    psq[r * 8 + wn]  = q;
                }
            }
        }
        __syncthreads();
        if (tid < BM) {
            float st = 0.0f, qt = 0.0f;
            #pragma unroll
            for (int i = 0; i < 8; i++) { st += psum[tid * 8 + i]; qt += psq[tid * 8 + i]; }
            float mean = st * (1.0f / 512.0f);
            float var  = qt * (1.0f / 512.0f) - mean * mean;
            stats[tid * 2]     = mean;
            stats[tid * 2 + 1] = rsqrtf(var + 1e-5f);
        }
        __syncthreads();

        #pragma unroll
        for (int mt = 0; mt < 4; mt++) {
            #pragma unroll
            for (int half = 0; half < 2; half++) {
                int r = mt * 16 + (lane >> 2) + half * 8;
                float mean = stats[r * 2];
                float rstd = stats[r * 2 + 1];
                float* orow = out + (size_t)(m0 + r) * N_DIM;
                #pragma unroll
                for (int nt = 0; nt < 8; nt++) {
                    int col = wn * 64 + nt * 8 + (lane & 3) * 2;
                    float ox = (fmaxf(acc[mt][nt][half * 2 + 0], 0.0f) - mean) * rstd * gsh[col]     + bsh[col];
                    float oy = (fmaxf(acc[mt][nt][half * 2 + 1], 0.0f) - mean) * rstd * gsh[col + 1] + bsh[col + 1];
                    stcs2(orow + col, ox, oy);
                }
            }
        }
        __syncthreads();   // psum/stats reuse next tile
    }
}

// ---------------------------------------------------------------------------
// Host launcher. Inputs: x, W_q, W_k, W_v, W_r, mix, gamma, beta
// ---------------------------------------------------------------------------
extern "C" void kernel_launch(void* const* d_in, const int* in_sizes, int n_in,
                              void* d_out, int out_size) {
    const float* x     = (const float*)d_in[0];
    const float* Wv    = (const float*)d_in[3];
    const float* Wr    = (const float*)d_in[4];
    const float* mix   = (const float*)d_in[5];
    const float* gamma = (const float*)d_in[6];
    const float* beta  = (const float*)d_in[7];
    float* out = (float*)d_out;

    cudaFuncSetAttribute(gemm_ln_kernel, cudaFuncAttributeMaxDynamicSharedMemorySize, SMEM_TOTAL);

    prep_kernel<<<(K_DIM * N_DIM + 255) / 256, 256>>>(Wv, Wr, mix);
    gemm_ln_kernel<<<GRID, NT, SMEM_TOTAL>>>(x, gamma, beta, out);
}

// round 15
// speedup vs baseline: 1.0474x; 1.0474x over previous
#include <cuda_runtime.h>
#include <cuda_fp16.h>
#include <cstdint>

// ============================================================================
// out = LayerNorm(relu(x @ (m*W_v + (1-m)*W_r)))   [attention path is identity:
// softmax rows sum to 1 and the reference einsum contracts the softmax axis]
//   x: [131072, 256] f32,  W: [256, 512] f32,  out: [131072, 512] f32
// R15 = R13 (warp-role specialization + persistent CTAs + cross-tile prefetch
// + ldcs/stcs, KC=64) with a 3-STAGE B RING at wait distance 2: the group
// retired at each region entry was committed two full MMA phases earlier, so
// the wait (and the barrier behind it) never exposes L2 transfer latency.
// Empty commits keep cp.async group accounting exact at the tail.
// fp16 mma.sync, 64x64 warp tiles, BM=64, NT=256.
// ============================================================================

static constexpr int K_DIM  = 256;
static constexpr int N_DIM  = 512;
static constexpr int BM     = 64;
static constexpr int KC     = 64;
static constexpr int NCH    = K_DIM / KC;   // 4
static constexpr int NTILES = 131072 / BM;  // 2048
static constexpr int NT     = 256;          // 8 warps; warp = 64 rows x 64 cols
static constexpr int GRID   = 148;

// SMEM layout (bytes)
static constexpr int SM_B  = 0;            // 3 stages x 64 KB = 192 KB
static constexpr int SM_A  = 196608;       // 2 stages x 8 KB = 16 KB
static constexpr int SM_GB = 212992;       // gamma/beta f32 = 4 KB
static constexpr int SM_PS = 217088;       // psum[64][8]+psq[64][8]+stats[64][2] = 4608
static constexpr int SMEM_TOTAL = 221696;

// Pre-swizzled fp16 B chunk images: off(n,kk) = swz(n*128 + kk*2), kk = k%64.
__device__ __align__(16) unsigned char g_Bimg[NCH][65536];

// ---------------------------------------------------------------------------
__device__ __forceinline__ uint32_t smem_u32(const void* p) {
    uint32_t r;
    asm("{ .reg .u64 t; cvta.to.shared.u64 t, %1; cvt.u32.u64 %0, t; }" : "=r"(r) : "l"(p));
    return r;
}
__host__ __device__ __forceinline__ uint32_t swz(uint32_t o) { return o ^ ((o >> 3) & 0x70); }

__device__ __forceinline__ void cp16(uint32_t d, const void* s) {
    asm volatile("cp.async.cg.shared.global [%0], [%1], 16;" :: "r"(d), "l"(s));
}
__device__ __forceinline__ void cp_commit() { asm volatile("cp.async.commit_group;"); }
template <int N>
__device__ __forceinline__ void cp_wait() { asm volatile("cp.async.wait_group %0;" :: "n"(N)); }

__device__ __forceinline__ float4 ldcs4(const float* p) {
    float4 v;
    asm volatile("ld.global.cs.v4.f32 {%0,%1,%2,%3}, [%4];"
                 : "=f"(v.x), "=f"(v.y), "=f"(v.z), "=f"(v.w) : "l"(p));
    return v;
}
__device__ __forceinline__ void stcs2(float* p, float a, float b) {
    asm volatile("st.global.cs.v2.f32 [%0], {%1,%2};" :: "l"(p), "f"(a), "f"(b) : "memory");
}

__device__ __forceinline__ void ldsm4(uint32_t* r, uint32_t a) {
    asm volatile("ldmatrix.sync.aligned.m8n8.x4.shared.b16 {%0,%1,%2,%3}, [%4];"
                 : "=r"(r[0]), "=r"(r[1]), "=r"(r[2]), "=r"(r[3]) : "r"(a));
}
__device__ __forceinline__ void hmma(float* c, const uint32_t* a, const uint32_t* b) {
    asm volatile("mma.sync.aligned.m16n8k16.row.col.f32.f16.f16.f32 "
                 "{%0,%1,%2,%3},{%4,%5,%6,%7},{%8,%9},{%0,%1,%2,%3};"
                 : "+f"(c[0]), "+f"(c[1]), "+f"(c[2]), "+f"(c[3])
                 : "r"(a[0]), "r"(a[1]), "r"(a[2]), "r"(a[3]), "r"(b[0]), "r"(b[1]));
}

// ---------------------------------------------------------------------------
// Prep: W_c = m*W_v + (1-m)*W_r -> fp16, pre-swizzled chunk images.
// ---------------------------------------------------------------------------
__global__ void prep_kernel(const float* __restrict__ Wv, const float* __restrict__ Wr,
                            const float* __restrict__ mix) {
    int gid = blockIdx.x * blockDim.x + threadIdx.x;
    if (gid >= K_DIM * N_DIM) return;
    int n = gid & 511;
    int k = gid >> 9;
    float m = 1.0f / (1.0f + expf(-mix[0]));
    float w = m * Wv[k * N_DIM + n] + (1.0f - m) * Wr[k * N_DIM + n];
    int c  = k >> 6;
    int kk = k & 63;
    uint32_t off = swz((uint32_t)(n * 128 + kk * 2));
    *(__half*)(&g_Bimg[c][off]) = __float2half(w);
}

// ---------------------------------------------------------------------------
// Persistent fused GEMM (fp16 mma.sync, specialized, deep B ring) + relu + LN
// ---------------------------------------------------------------------------
__global__ void __launch_bounds__(NT, 1)
gemm_ln_kernel(const float* __restrict__ x, const float* __restrict__ gamma,
               const float* __restrict__ beta, float* __restrict__ out) {
    extern __shared__ char smem[];
    const uint32_t sb = smem_u32(smem);
    const int tid  = threadIdx.x;
    const int wn   = tid >> 5;    // warp 0..7 -> 64-col slice, all 64 rows
    const int lane = tid & 31;
    const bool loader = (wn < 4); // one loader warp per SMSP
    const int bid  = blockIdx.x;

    // gamma/beta into smem (once)
    {
        float* gsh = (float*)(smem + SM_GB);
        for (int i = tid; i < N_DIM; i += NT) {
            gsh[i]         = gamma[i];
            gsh[N_DIM + i] = beta[i];
        }
    }

    // ldmatrix base offsets
    const uint32_t arow = (uint32_t)((lane & 15) * 128 + (lane >> 4) * 16);
    const uint32_t brow = (uint32_t)((wn * 64 + ((lane >> 4) & 1) * 8 + (lane & 7)) * 128
                                     + ((lane >> 3) & 1) * 16);

    // Loader A indexing: 1024 float4 per chunk over 128 loader threads -> 8 each
    int arowi[8], asegi[8];
    uint32_t asoff[8];
    #pragma unroll
    for (int i = 0; i < 8; i++) {
        int idx = tid + i * 128;
        arowi[i] = idx >> 4;
        asegi[i] = (idx & 15) * 4;
        asoff[i] = swz((uint32_t)((idx >> 4) * 128 + (idx & 15) * 8));
    }

    float* psum  = (float*)(smem + SM_PS);
    float* psq   = psum + 512;
    float* stats = psq + 512;
    const float* gsh = (const float*)(smem + SM_GB);
    const float* bsh = gsh + N_DIM;

    float4 av[8];
    // ---- one-time prologue (loader warps): B regions 0,1 in flight; A c0 STS; c1 LDG ----
    if (loader) {
        #pragma unroll
        for (int s = 0; s < 2; s++) {
            #pragma unroll
            for (int i = 0; i < 32; i++) {
                int j = tid + i * 128;
                cp16(sb + SM_B + s * 65536 + j * 16, &g_Bimg[s][j * 16]);
            }
            cp_commit();
        }
        const size_t mb = (size_t)bid * BM;
        #pragma unroll
        for (int i = 0; i < 8; i++)
            av[i] = ldcs4(x + (mb + arowi[i]) * K_DIM + asegi[i]);
        #pragma unroll
        for (int i = 0; i < 8; i++) {
            __half2 h01 = __floats2half2_rn(av[i].x, av[i].y);
            __half2 h23 = __floats2half2_rn(av[i].z, av[i].w);
            *(uint2*)(smem + SM_A + asoff[i]) = make_uint2(*(uint32_t*)&h01, *(uint32_t*)&h23);
        }
        #pragma unroll
        for (int i = 0; i < 8; i++)
            av[i] = ldcs4(x + (mb + arowi[i]) * K_DIM + KC + asegi[i]);
    }

    int r = 0;   // absolute region index; B image = r & 3, B stage = r % 3
    for (int t = bid; t < NTILES; t += GRID) {
        const size_t m0 = (size_t)t * BM;
        const bool last_tile = (t + GRID >= NTILES);

        float acc[4][8][4];
        #pragma unroll
        for (int mt = 0; mt < 4; mt++)
            #pragma unroll
            for (int nt = 0; nt < 8; nt++)
                #pragma unroll
                for (int i = 0; i < 4; i++) acc[mt][nt][i] = 0.0f;

        #pragma unroll
        for (int c = 0; c < NCH; c++, r++) {
            const int stage = r % 3;
            // retire the group for THIS region (committed 2 regions ago);
            // exact accounting guaranteed by one commit per region (possibly empty)
            if (loader) cp_wait<1>();
            __syncthreads();               // publish stage; order chunk reuse

            if (loader) {
                // A: STS next chunk, LDG chunk after (cross-tile at the seam)
                const bool has_nextA = !(last_tile && c == NCH - 1);
                if (has_nextA) {
                    const int nst = (c + 1) & 1;
                    #pragma unroll
                    for (int i = 0; i < 8; i++) {
                        __half2 h01 = __floats2half2_rn(av[i].x, av[i].y);
                        __half2 h23 = __floats2half2_rn(av[i].z, av[i].w);
                        *(uint2*)(smem + SM_A + nst * 8192 + asoff[i]) =
                            make_uint2(*(uint32_t*)&h01, *(uint32_t*)&h23);
                    }
                    if (c < NCH - 2) {
                        #pragma unroll
                        for (int i = 0; i < 8; i++)
                            av[i] = ldcs4(x + (m0 + arowi[i]) * K_DIM + (c + 2) * KC + asegi[i]);
                    } else if (!last_tile) {
                        const size_t mn = (size_t)(t + GRID) * BM;
                        #pragma unroll
                        for (int i = 0; i < 8; i++)
                            av[i] = ldcs4(x + (mn + arowi[i]) * K_DIM + (c - 2) * KC + asegi[i]);
                    }
                }
                // B for region r+2 into stage (r+2)%3 (last read region r-1,
                // ordered by this region's entry barrier). Commit EVERY region.
                const bool has_nextB = !(last_tile && c >= NCH - 2);
                if (has_nextB) {
                    const uint32_t dst = sb + SM_B + ((r + 2) % 3) * 65536;
                    const unsigned char* bimg = &g_Bimg[(r + 2) & 3][0];
                    #pragma unroll
                    for (int i = 0; i < 32; i++) {
                        int j = tid + i * 128;
                        cp16(dst + j * 16, bimg + j * 16);
                    }
                }
                cp_commit();
            }

            // ---- MMA chunk (all warps; MMA-only warps start immediately) ----
            const uint32_t Ab = sb + SM_A + (c & 1) * 8192;
            const uint32_t Bb = sb + SM_B + stage * 65536;
            uint32_t af[2][4][4];
            #pragma unroll
            for (int mt = 0; mt < 4; mt++)
                ldsm4(af[0][mt], Ab + swz(arow + mt * 2048));
            #pragma unroll
            for (int ks = 0; ks < 4; ks++) {
                const int cur = ks & 1, nxt = cur ^ 1;
                if (ks < 3)
                    #pragma unroll
                    for (int mt = 0; mt < 4; mt++)
                        ldsm4(af[nxt][mt], Ab + swz(arow + mt * 2048 + (ks + 1) * 32));
                #pragma unroll
                for (int bt = 0; bt < 4; bt++) {
                    uint32_t bh[4];
                    ldsm4(bh, Bb + swz(brow + bt * 2048 + ks * 32));
                    #pragma unroll
                    for (int mt = 0; mt < 4; mt++) {
                        hmma(acc[mt][2 * bt],     af[cur][mt], &bh[0]);
                        hmma(acc[mt][2 * bt + 1], af[cur][mt], &bh[2]);
                    }
                }
            }
        }

        // ---------------- Epilogue: relu + LayerNorm(512) ----------------
        #pragma unroll
        for (int mt = 0; mt < 4; mt++) {
            #pragma unroll
            for (int half = 0; half < 2; half++) {
                float s = 0.0f, q = 0.0f;
                #pragma unroll
                for (int nt = 0; nt < 8; nt++) {
                    float v0 = fmaxf(acc[mt][nt][half * 2 + 0], 0.0f);
                    float v1 = fmaxf(acc[mt][nt][half * 2 + 1], 0.0f);
                    s += v0 + v1;
                    q = fmaf(v0, v0, q);
                    q = fmaf(v1, v1, q);
                }
                s += __shfl_xor_sync(0xFFFFFFFFu, s, 1);
                q += __shfl_xor_sync(0xFFFFFFFFu, q, 1);
                s += __shfl_xor_sync(0xFFFFFFFFu, s, 2);
                q += __shfl_xor_sync(0xFFFFFFFFu, q, 2);
                if ((lane & 3) == 0) {
                    int rr = mt * 16 + (lane >> 2) + half * 8;
                    psum[rr * 8 + wn] = s;
                    psq[rr * 8 + wn]  = q;
                }
            }
        }
        __syncthreads();
        if (tid < BM) {
            float st = 0.0f, qt = 0.0f;
            #pragma unroll
            for (int i = 0; i < 8; i++) { st += psum[tid * 8 + i]; qt += psq[tid * 8 + i]; }
            float mean = st * (1.0f / 512.0f);
            float var  = qt * (1.0f / 512.0f) - mean * mean;
            stats[tid * 2]     = mean;
            stats[tid * 2 + 1] = rsqrtf(var + 1e-5f);
        }
        __syncthreads();

        #pragma unroll
        for (int mt = 0; mt < 4; mt++) {
            #pragma unroll
            for (int half = 0; half < 2; half++) {
                int rr = mt * 16 + (lane >> 2) + half * 8;
                float mean = stats[rr * 2];
                float rstd = stats[rr * 2 + 1];
                float* orow = out + (size_t)(m0 + rr) * N_DIM;
                #pragma unroll
                for (int nt = 0; nt < 8; nt++) {
                    int col = wn * 64 + nt * 8 + (lane & 3) * 2;
                    float ox = (fmaxf(acc[mt][nt][half * 2 + 0], 0.0f) - mean) * rstd * gsh[col]     + bsh[col];
                    float oy = (fmaxf(acc[mt][nt][half * 2 + 1], 0.0f) - mean) * rstd * gsh[col + 1] + bsh[col + 1];
                    stcs2(orow + col, ox, oy);
                }
            }
        }
        // no trailing barrier: psum/psq reuse is ordered by the 4 region-entry
        // barriers of the next tile before the next epilogue writes them
    }
}

// ---------------------------------------------------------------------------
// Host launcher. Inputs: x, W_q, W_k, W_v, W_r, mix, gamma, beta
// ---------------------------------------------------------------------------
extern "C" void kernel_launch(void* const* d_in, const int* in_sizes, int n_in,
                              void* d_out, int out_size) {
    const float* x     = (const float*)d_in[0];
    const float* Wv    = (const float*)d_in[3];
    const float* Wr    = (const float*)d_in[4];
    const float* mix   = (const float*)d_in[5];
    const float* gamma = (const float*)d_in[6];
    const float* beta  = (const float*)d_in[7];
    float* out = (float*)d_out;

    cudaFuncSetAttribute(gemm_ln_kernel, cudaFuncAttributeMaxDynamicSharedMemorySize, SMEM_TOTAL);

    prep_kernel<<<(K_DIM * N_DIM + 255) / 256, 256>>>(Wv, Wr, mix);
    gemm_ln_kernel<<<GRID, NT, SMEM_TOTAL>>>(x, gamma, beta, out);
}